// round 4
// baseline (speedup 1.0000x reference)
#include <cuda_runtime.h>
#include <cstdint>

#define BB 4
#define SS 4096
#define DD 2048
#define RR 4
#define RFF 16
#define NROWS (BB*SS)   // 16384
#define TRU 8           // rows per block in k_u
#define TRM 16          // rows per block in k_main
#define EPS 1e-6f

typedef unsigned long long u64;

// -------- device scratch (no allocation allowed) --------
__device__ __align__(16) float g_ssq[NROWS];
__device__ __align__(16) float g_u  [RR*NROWS];   // planar [r][row], pre-scaled by rmsnorm
__device__ __align__(16) float g_pu [NROWS*RR];   // row-major
__device__ __align__(16) float g_pw1[NROWS*RFF];  // row-major
__device__ __align__(16) float g_h  [RR*NROWS];   // planar [r][row]
__device__ __align__(16) float g_g  [NROWS*RFF];  // row-major
__device__ __align__(16) float g_Vt [RR*DD];      // w*V transposed
__device__ __align__(16) float g_Ut [RR*DD];      // U transposed
__device__ __align__(16) float g_W1t[RFF*DD];     // w*W1 transposed
__device__ float g_G[16];    // U^T U
__device__ float g_M[64];    // U^T (w*W1)
__device__ float g_a[RR];

// -------- packed f32x2 helpers --------
__device__ __forceinline__ u64 fma2(u64 a, u64 b, u64 c){
    u64 d; asm("fma.rn.f32x2 %0, %1, %2, %3;" : "=l"(d) : "l"(a), "l"(b), "l"(c)); return d;
}
__device__ __forceinline__ u64 pack2(float x, float y){
    u64 r; asm("mov.b64 %0, {%1, %2};" : "=l"(r) : "f"(x), "f"(y)); return r;
}
__device__ __forceinline__ float2 unpack2(u64 p){
    float2 f; asm("mov.b64 {%0, %1}, %2;" : "=f"(f.x), "=f"(f.y) : "l"(p)); return f;
}

__device__ __forceinline__ float warp_sum(float v){
    v += __shfl_down_sync(0xffffffffu, v, 16);
    v += __shfl_down_sync(0xffffffffu, v, 8);
    v += __shfl_down_sync(0xffffffffu, v, 4);
    v += __shfl_down_sync(0xffffffffu, v, 2);
    v += __shfl_down_sync(0xffffffffu, v, 1);
    return v;
}

// butterfly reduce-scatter: after call, each lane holds warp-total of
// value index (lane & (N-1)). N power of 2.
template<int N>
__device__ __forceinline__ float rs_reduce(float (&v)[N], int lane){
    #pragma unroll
    for (int s = N/2; s >= 1; s >>= 1){
        bool up = (lane & s) != 0;
        #pragma unroll
        for (int i = 0; i < s; i++){
            float send = up ? v[i] : v[i+s];
            float keep = up ? v[i+s] : v[i];
            v[i] = keep + __shfl_xor_sync(0xffffffffu, send, s);
        }
    }
    float r = v[0];
    #pragma unroll
    for (int s = N; s < 32; s <<= 1)
        r += __shfl_xor_sync(0xffffffffu, r, s);
    return r;
}

__device__ __forceinline__ float gelu_tanh(float x){
    float c = 0.7978845608028654f * (x + 0.044715f * x * x * x);
    return 0.5f * x * (1.0f + tanhf(c));
}

// ======================= prep: transpose/fold weights =======================
__global__ void k_prep(const float* __restrict__ norm_w, const float* __restrict__ V,
                       const float* __restrict__ U, const float* __restrict__ a_logit,
                       const float* __restrict__ W1){
    int d = blockIdx.x * blockDim.x + threadIdx.x;
    if (d < DD){
        float w = norm_w[d];
        #pragma unroll
        for (int r = 0; r < RR; r++){
            g_Vt[r*DD + d] = w * V[d*RR + r];
            g_Ut[r*DD + d] = U[d*RR + r];
        }
        #pragma unroll
        for (int r = 0; r < RFF; r++)
            g_W1t[r*DD + d] = w * W1[d*RFF + r];
    }
    if (d < RR) g_a[d] = 1.0f / (1.0f + expf(-a_logit[d]));
}

// G = U^T U (16 dots), M = U^T (w*W1) (64 dots); one block per dot.
__global__ void k_prep2(const float* __restrict__ U){
    int j = blockIdx.x;
    int tid = threadIdx.x;
    float s = 0.f;
    if (j < 16){
        int k = j >> 2, q = j & 3;
        for (int d = tid; d < DD; d += 256)
            s += U[d*RR + k] * U[d*RR + q];
    } else {
        int k = (j-16) >> 4, r = (j-16) & 15;
        for (int d = tid; d < DD; d += 256)
            s += U[d*RR + k] * g_W1t[r*DD + d];
    }
    s = warp_sum(s);
    __shared__ float sh[8];
    if ((tid & 31) == 0) sh[tid >> 5] = s;
    __syncthreads();
    if (tid == 0){
        float t = 0.f;
        #pragma unroll
        for (int i = 0; i < 8; i++) t += sh[i];
        if (j < 16) g_G[j] = t; else g_M[j-16] = t;
    }
}

// ======================= k_u: 25 dots per row over x =======================
// per row: ssq(x), u = rmsnorm-scaled (wV)^T x (4), pU = U^T x (4), pW1 = (wW1)^T x (16)
__global__ void __launch_bounds__(512) k_u(const float* __restrict__ x){
    const int row0 = blockIdx.x * TRU;
    const int tid = threadIdx.x;
    const int w = tid >> 5, l = tid & 31;
    __shared__ float sred[TRU][25][17];
    __shared__ float tot[TRU][25];

    ulonglong2 xp[TRU];
    #pragma unroll
    for (int row = 0; row < TRU; row++)
        xp[row] = reinterpret_cast<const ulonglong2*>(x)[(size_t)(row0+row)*(DD/4) + tid];

    // ---- pass A: ssq + V(4) + U(4) ----
    {
        ulonglong2 wp[8];
        #pragma unroll
        for (int r = 0; r < 4; r++){
            wp[r]   = reinterpret_cast<const ulonglong2*>(g_Vt)[r*(DD/4) + tid];
            wp[4+r] = reinterpret_cast<const ulonglong2*>(g_Ut)[r*(DD/4) + tid];
        }
        #pragma unroll
        for (int row = 0; row < TRU; row++){
            float2 fs = unpack2(fma2(xp[row].x, xp[row].x, fma2(xp[row].y, xp[row].y, 0ull)));
            float ss = warp_sum(fs.x + fs.y);
            float v[8];
            #pragma unroll
            for (int j = 0; j < 8; j++){
                float2 f = unpack2(fma2(xp[row].x, wp[j].x, fma2(xp[row].y, wp[j].y, 0ull)));
                v[j] = f.x + f.y;
            }
            float rv = rs_reduce<8>(v, l);
            if (l == 0) sred[row][0][w] = ss;
            if (l < 8)  sred[row][1+l][w] = rv;
        }
    }
    // ---- passes B,C: W1 ranks, 8 at a time ----
    #pragma unroll
    for (int half = 0; half < 2; half++){
        ulonglong2 wp[8];
        #pragma unroll
        for (int r = 0; r < 8; r++)
            wp[r] = reinterpret_cast<const ulonglong2*>(g_W1t)[(half*8+r)*(DD/4) + tid];
        #pragma unroll
        for (int row = 0; row < TRU; row++){
            float v[8];
            #pragma unroll
            for (int j = 0; j < 8; j++){
                float2 f = unpack2(fma2(xp[row].x, wp[j].x, fma2(xp[row].y, wp[j].y, 0ull)));
                v[j] = f.x + f.y;
            }
            float rv = rs_reduce<8>(v, l);
            if (l < 8) sred[row][9 + half*8 + l][w] = rv;
        }
    }
    __syncthreads();

    if (tid < TRU*25){
        int row = tid / 25, val = tid % 25;
        float s = 0.f;
        #pragma unroll
        for (int ww = 0; ww < 16; ww++) s += sred[row][val][ww];
        tot[row][val] = s;
    }
    __syncthreads();
    if (tid < TRU*25){
        int row = tid / 25, val = tid % 25;
        int gr = row0 + row;
        float s = tot[row][val];
        if (val == 0) g_ssq[gr] = s;
        else if (val < 5){
            float scale = rsqrtf(tot[row][0] * (1.0f/DD) + EPS);
            g_u[(val-1)*NROWS + gr] = scale * s;
        }
        else if (val < 9) g_pu[(size_t)gr*RR + (val-5)] = s;
        else              g_pw1[(size_t)gr*RFF + (val-9)] = s;
    }
}

// ======================= k_scan: warp-parallel linear-recurrence scan =======================
// grid = BB*RR, 256 threads, 16 elements per thread, coalesced planar u.
__global__ void __launch_bounds__(256) k_scan(){
    const int b = blockIdx.x >> 2;
    const int r = blockIdx.x & 3;
    const float a = g_a[r];
    const int tid = threadIdx.x, l = tid & 31, w = tid >> 5;
    const float* u = g_u + r*NROWS + b*SS;

    float uu[16];
    float4* uu4 = reinterpret_cast<float4*>(uu);
    #pragma unroll
    for (int i = 0; i < 4; i++)
        uu4[i] = reinterpret_cast<const float4*>(u)[tid*4 + i];

    float f = 0.f;
    #pragma unroll
    for (int i = 0; i < 16; i++) f = a*f + uu[i];

    // A = a^16
    float A = a; A *= A; A *= A; A *= A; A *= A;

    // warp inclusive scan of chunk values with ratio A: I_j = f_j + A*I_{j-1}
    float I = f, As = A;
    #pragma unroll
    for (int st = 0; st < 5; st++){
        float gg = __shfl_up_sync(0xffffffffu, I, 1 << st);
        if (l >= (1 << st)) I += As * gg;
        As *= As;
    }

    __shared__ float Tw[8], Ww[8];
    if (l == 31) Tw[w] = I;
    __syncthreads();
    if (tid == 0){
        float A32 = A;                         // a^16
        #pragma unroll
        for (int k = 0; k < 5; k++) A32 *= A32; // a^512
        float c = 0.f;
        #pragma unroll
        for (int j = 0; j < 8; j++){ Ww[j] = c; c = A32*c + Tw[j]; }
    }
    __syncthreads();

    // A^lane
    float Al = 1.f, p = A;
    #pragma unroll
    for (int bit = 0; bit < 5; bit++){ if ((l >> bit) & 1) Al *= p; p *= p; }
    float Iprev = __shfl_up_sync(0xffffffffu, I, 1);
    float c = ((l == 0) ? 0.f : Iprev) + Al * Ww[w];

    float* hh = g_h + r*NROWS + b*SS;
    float h = c;
    float ho[16];
    #pragma unroll
    for (int i = 0; i < 16; i++){ h = a*h + uu[i]; ho[i] = h; }
    float4* ho4 = reinterpret_cast<float4*>(ho);
    #pragma unroll
    for (int i = 0; i < 4; i++)
        reinterpret_cast<float4*>(hh)[tid*4 + i] = ho4[i];
}

// ======================= k_post: per-row scale1, t, gelu =======================
__global__ void __launch_bounds__(256) k_post(){
    __shared__ float sG[16], sM[64];
    int tid = threadIdx.x;
    if (tid < 16) sG[tid] = g_G[tid];
    if (tid < 64) sM[tid] = g_M[tid];
    __syncthreads();

    int row = blockIdx.x * 256 + tid;
    float h[4], p[4];
    #pragma unroll
    for (int k = 0; k < 4; k++) h[k] = g_h[k*NROWS + row];
    float4 p4 = reinterpret_cast<const float4*>(g_pu)[row];
    p[0]=p4.x; p[1]=p4.y; p[2]=p4.z; p[3]=p4.w;

    float s1 = g_ssq[row];
    #pragma unroll
    for (int k = 0; k < 4; k++) s1 += 2.0f * h[k] * p[k];
    #pragma unroll
    for (int k = 0; k < 4; k++)
        #pragma unroll
        for (int q = 0; q < 4; q++) s1 += h[k] * h[q] * sG[k*4+q];
    float scale = rsqrtf(s1 * (1.0f/DD) + EPS);

    #pragma unroll
    for (int r = 0; r < RFF; r++){
        float t = g_pw1[(size_t)row*RFF + r];
        #pragma unroll
        for (int k = 0; k < 4; k++) t += h[k] * sM[k*16 + r];
        g_g[(size_t)row*RFF + r] = gelu_tanh(t * scale);
    }
}

// ======================= k_main: out = x + U h + g @ W2 (pure stream, split-D) =======================
// grid = (NROWS/TRM, 2); each block does 16 rows x half the D dimension.
__global__ void __launch_bounds__(512, 2) k_main(const float* __restrict__ x,
                                                 const float* __restrict__ W2,
                                                 float* __restrict__ out){
    const int row0 = blockIdx.x * TRM;
    const int tid  = threadIdx.x;
    const int pidx = blockIdx.y * 512 + tid;   // f32-pair index within row

    u64 utp[4], w2p[16];
    #pragma unroll
    for (int k = 0; k < 4; k++)
        utp[k] = reinterpret_cast<const u64*>(g_Ut)[k*(DD/2) + pidx];
    #pragma unroll
    for (int r = 0; r < RFF; r++)
        w2p[r] = reinterpret_cast<const u64*>(W2)[r*(DD/2) + pidx];

    __shared__ u64 hg[TRM][20];
    if (tid < TRM*20){
        int row = tid / 20, j = tid % 20;
        float v = (j < 4) ? g_h[j*NROWS + row0 + row]
                          : g_g[(size_t)(row0+row)*RFF + (j-4)];
        hg[row][j] = pack2(v, v);
    }
    __syncthreads();

    const u64* xr = reinterpret_cast<const u64*>(x)   + (size_t)row0*(DD/2) + pidx;
    u64*       orp = reinterpret_cast<u64*>(out)      + (size_t)row0*(DD/2) + pidx;

    u64 xa = xr[0];
    #pragma unroll
    for (int row = 0; row < TRM; row++){
        u64 xn = xa;
        if (row + 1 < TRM) xn = xr[(size_t)(row+1)*(DD/2)];
        u64 acc = xa;
        #pragma unroll
        for (int k = 0; k < 4; k++)  acc = fma2(hg[row][k],    utp[k], acc);
        #pragma unroll
        for (int r = 0; r < RFF; r++) acc = fma2(hg[row][4+r], w2p[r], acc);
        orp[(size_t)row*(DD/2)] = acc;
        xa = xn;
    }
}

// ======================= launch =======================
extern "C" void kernel_launch(void* const* d_in, const int* in_sizes, int n_in,
                              void* d_out, int out_size){
    const float* x       = (const float*)d_in[0];
    const float* norm_w  = (const float*)d_in[1];
    const float* V       = (const float*)d_in[2];
    const float* U       = (const float*)d_in[3];
    const float* a_logit = (const float*)d_in[4];
    const float* W1      = (const float*)d_in[5];
    const float* W2      = (const float*)d_in[6];
    float* out = (float*)d_out;

    k_prep <<<8, 256>>>(norm_w, V, U, a_logit, W1);
    k_prep2<<<80, 256>>>(U);
    k_u    <<<NROWS/TRU, 512>>>(x);
    k_scan <<<BB*RR, 128+128>>>();
    k_post <<<NROWS/256, 256>>>();
    dim3 gm(NROWS/TRM, 2);
    k_main <<<gm, 512>>>(x, W2, out);
}

// round 7
// speedup vs baseline: 1.1248x; 1.1248x over previous
#include <cuda_runtime.h>
#include <cstdint>

#define BB 4
#define SS 4096
#define DD 2048
#define RR 4
#define RFF 16
#define NROWS (BB*SS)   // 16384
#define TRU 8           // rows per block in k_u
#define TRM 16          // rows per block in k_main
#define EPS 1e-6f

typedef unsigned long long u64;

// -------- device scratch (no allocation allowed) --------
__device__ __align__(16) float g_ssq[NROWS];
__device__ __align__(16) float g_u  [RR*NROWS];   // planar [r][row], pre-scaled by rmsnorm
__device__ __align__(16) float g_pu [NROWS*RR];   // row-major
__device__ __align__(16) float g_pw1[NROWS*RFF];  // row-major
__device__ __align__(16) float g_h  [RR*NROWS];   // planar [r][row]
__device__ __align__(16) float g_g  [NROWS*RFF];  // row-major
__device__ __align__(16) float g_Vt [RR*DD];      // w*V transposed
__device__ __align__(16) float g_Ut [RR*DD];      // U transposed
__device__ __align__(16) float g_W1t[RFF*DD];     // w*W1 transposed
__device__ float g_G[16];    // U^T U
__device__ float g_M[64];    // U^T (w*W1)
__device__ float g_a[RR];

// -------- packed f32x2 helpers --------
__device__ __forceinline__ u64 fma2(u64 a, u64 b, u64 c){
    u64 d; asm("fma.rn.f32x2 %0, %1, %2, %3;" : "=l"(d) : "l"(a), "l"(b), "l"(c)); return d;
}
__device__ __forceinline__ u64 add2(u64 a, u64 b){
    u64 d; asm("add.rn.f32x2 %0, %1, %2;" : "=l"(d) : "l"(a), "l"(b)); return d;
}
__device__ __forceinline__ u64 pack2(float x, float y){
    u64 r; asm("mov.b64 %0, {%1, %2};" : "=l"(r) : "f"(x), "f"(y)); return r;
}
__device__ __forceinline__ float2 unpack2(u64 p){
    float2 f; asm("mov.b64 {%0, %1}, %2;" : "=f"(f.x), "=f"(f.y) : "l"(p)); return f;
}
__device__ __forceinline__ float warp_sum(float v){
    v += __shfl_down_sync(0xffffffffu, v, 16);
    v += __shfl_down_sync(0xffffffffu, v, 8);
    v += __shfl_down_sync(0xffffffffu, v, 4);
    v += __shfl_down_sync(0xffffffffu, v, 2);
    v += __shfl_down_sync(0xffffffffu, v, 1);
    return v;
}
// butterfly reduce-scatter: after call, each lane holds warp-total of
// value index (lane & (N-1)). N power of 2.
template<int N>
__device__ __forceinline__ float rs_reduce(float (&v)[N], int lane){
    #pragma unroll
    for (int s = N/2; s >= 1; s >>= 1){
        bool up = (lane & s) != 0;
        #pragma unroll
        for (int i = 0; i < s; i++){
            float send = up ? v[i] : v[i+s];
            float keep = up ? v[i+s] : v[i];
            v[i] = keep + __shfl_xor_sync(0xffffffffu, send, s);
        }
    }
    float r = v[0];
    #pragma unroll
    for (int s = N; s < 32; s <<= 1)
        r += __shfl_xor_sync(0xffffffffu, r, s);
    return r;
}
__device__ __forceinline__ float gelu_tanh(float x){
    float c = 0.7978845608028654f * (x + 0.044715f * x * x * x);
    return 0.5f * x * (1.0f + tanhf(c));
}

// ======================= prep (fused): transpose/fold + G/M dots =======================
__global__ void k_prep_all(const float* __restrict__ norm_w, const float* __restrict__ V,
                           const float* __restrict__ U, const float* __restrict__ a_logit,
                           const float* __restrict__ W1){
    int tid = threadIdx.x;
    if (blockIdx.x < 8){
        int d = blockIdx.x * 256 + tid;
        float w = norm_w[d];
        #pragma unroll
        for (int r = 0; r < RR; r++){
            g_Vt[r*DD + d] = w * V[d*RR + r];
            g_Ut[r*DD + d] = U[d*RR + r];
        }
        #pragma unroll
        for (int r = 0; r < RFF; r++)
            g_W1t[r*DD + d] = w * W1[d*RFF + r];
        if (blockIdx.x == 0 && tid < RR) g_a[tid] = 1.0f / (1.0f + expf(-a_logit[tid]));
    } else {
        int j = blockIdx.x - 8;   // 0..79
        float s = 0.f;
        if (j < 16){
            int k = j >> 2, q = j & 3;
            for (int d = tid; d < DD; d += 256)
                s += U[d*RR + k] * U[d*RR + q];
        } else {
            int k = (j-16) >> 4, r = (j-16) & 15;
            for (int d = tid; d < DD; d += 256)
                s += U[d*RR + k] * norm_w[d] * W1[d*RFF + r];
        }
        s = warp_sum(s);
        __shared__ float sh[8];
        if ((tid & 31) == 0) sh[tid >> 5] = s;
        __syncthreads();
        if (tid == 0){
            float t = 0.f;
            #pragma unroll
            for (int i = 0; i < 8; i++) t += sh[i];
            if (j < 16) g_G[j] = t; else g_M[j-16] = t;
        }
    }
}

// ======================= k_u: 25 dots per row over x =======================
// per row: ssq(x), u = scaled (wV)^T x (4), pU = U^T x (4), pW1 = (wW1)^T x (16)
__global__ void __launch_bounds__(512) k_u(const float* __restrict__ x){
    const int row0 = blockIdx.x * TRU;
    const int tid = threadIdx.x;
    const int w = tid >> 5, l = tid & 31;
    __shared__ float sred[TRU][25][17];
    __shared__ float tot[TRU][25];

    ulonglong2 xp[TRU];
    #pragma unroll
    for (int row = 0; row < TRU; row++)
        xp[row] = reinterpret_cast<const ulonglong2*>(x)[(size_t)(row0+row)*(DD/4) + tid];

    // ---- pass A: ssq + V(4) + U(4) -> slots 0..8 ----
    {
        ulonglong2 wp[8];
        #pragma unroll
        for (int r = 0; r < 4; r++){
            wp[r]   = reinterpret_cast<const ulonglong2*>(g_Vt)[r*(DD/4) + tid];
            wp[4+r] = reinterpret_cast<const ulonglong2*>(g_Ut)[r*(DD/4) + tid];
        }
        #pragma unroll
        for (int row = 0; row < TRU; row++){
            float2 fs = unpack2(fma2(xp[row].x, xp[row].x, fma2(xp[row].y, xp[row].y, 0ull)));
            float ss = warp_sum(fs.x + fs.y);
            float v[8];
            #pragma unroll
            for (int j = 0; j < 8; j++){
                float2 f = unpack2(fma2(xp[row].x, wp[j].x, fma2(xp[row].y, wp[j].y, 0ull)));
                v[j] = f.x + f.y;
            }
            float rv = rs_reduce<8>(v, l);
            if (l == 0) sred[row][0][w] = ss;
            if (l < 8)  sred[row][1+l][w] = rv;
        }
    }
    __syncthreads();   // scheduling fence: keep weight-pass register sets disjoint

    // ---- passes B,C: W1 ranks, 8 at a time -> slots 9..24 ----
    #pragma unroll
    for (int half = 0; half < 2; half++){
        ulonglong2 wp[8];
        #pragma unroll
        for (int r = 0; r < 8; r++)
            wp[r] = reinterpret_cast<const ulonglong2*>(g_W1t)[(half*8+r)*(DD/4) + tid];
        #pragma unroll
        for (int row = 0; row < TRU; row++){
            float v[8];
            #pragma unroll
            for (int j = 0; j < 8; j++){
                float2 f = unpack2(fma2(xp[row].x, wp[j].x, fma2(xp[row].y, wp[j].y, 0ull)));
                v[j] = f.x + f.y;
            }
            float rv = rs_reduce<8>(v, l);
            if (l < 8) sred[row][9 + half*8 + l][w] = rv;
        }
        __syncthreads();
    }

    if (tid < TRU*25){
        int row = tid / 25, val = tid % 25;
        float s = 0.f;
        #pragma unroll
        for (int ww = 0; ww < 16; ww++) s += sred[row][val][ww];
        tot[row][val] = s;
    }
    __syncthreads();
    if (tid < TRU*25){
        int row = tid / 25, val = tid % 25;
        int gr = row0 + row;
        float s = tot[row][val];
        if (val == 0) g_ssq[gr] = s;
        else if (val < 5){
            float scale = rsqrtf(tot[row][0] * (1.0f/DD) + EPS);
            g_u[(val-1)*NROWS + gr] = scale * s;
        }
        else if (val < 9) g_pu[(size_t)gr*RR + (val-5)] = s;
        else              g_pw1[(size_t)gr*RFF + (val-9)] = s;
    }
}

// ======================= k_scan: warp-parallel linear-recurrence scan =======================
__global__ void __launch_bounds__(256) k_scan(){
    const int b = blockIdx.x >> 2;
    const int r = blockIdx.x & 3;
    const float a = g_a[r];
    const int tid = threadIdx.x, l = tid & 31, w = tid >> 5;
    const float* u = g_u + r*NROWS + b*SS;

    float uu[16];
    float4* uu4 = reinterpret_cast<float4*>(uu);
    #pragma unroll
    for (int i = 0; i < 4; i++)
        uu4[i] = reinterpret_cast<const float4*>(u)[tid*4 + i];

    float f = 0.f;
    #pragma unroll
    for (int i = 0; i < 16; i++) f = a*f + uu[i];

    float A = a; A *= A; A *= A; A *= A; A *= A;   // a^16

    float I = f, As = A;
    #pragma unroll
    for (int st = 0; st < 5; st++){
        float gg = __shfl_up_sync(0xffffffffu, I, 1 << st);
        if (l >= (1 << st)) I += As * gg;
        As *= As;
    }

    __shared__ float Tw[8], Ww[8];
    if (l == 31) Tw[w] = I;
    __syncthreads();
    if (tid == 0){
        float A32 = A;
        #pragma unroll
        for (int k = 0; k < 5; k++) A32 *= A32;  // a^512
        float c = 0.f;
        #pragma unroll
        for (int j = 0; j < 8; j++){ Ww[j] = c; c = A32*c + Tw[j]; }
    }
    __syncthreads();

    float Al = 1.f, p = A;
    #pragma unroll
    for (int bit = 0; bit < 5; bit++){ if ((l >> bit) & 1) Al *= p; p *= p; }
    float Iprev = __shfl_up_sync(0xffffffffu, I, 1);
    float c = ((l == 0) ? 0.f : Iprev) + Al * Ww[w];

    float* hh = g_h + r*NROWS + b*SS;
    float h = c;
    float ho[16];
    #pragma unroll
    for (int i = 0; i < 16; i++){ h = a*h + uu[i]; ho[i] = h; }
    float4* ho4 = reinterpret_cast<float4*>(ho);
    #pragma unroll
    for (int i = 0; i < 4; i++)
        reinterpret_cast<float4*>(hh)[tid*4 + i] = ho4[i];
}

// ======================= k_post: per-row scale1, t, gelu =======================
__global__ void __launch_bounds__(256) k_post(){
    __shared__ float sG[16], sM[64];
    int tid = threadIdx.x;
    if (tid < 16) sG[tid] = g_G[tid];
    if (tid < 64) sM[tid] = g_M[tid];
    __syncthreads();

    int row = blockIdx.x * 256 + tid;
    float h[4], p[4];
    #pragma unroll
    for (int k = 0; k < 4; k++) h[k] = g_h[k*NROWS + row];
    float4 p4 = reinterpret_cast<const float4*>(g_pu)[row];
    p[0]=p4.x; p[1]=p4.y; p[2]=p4.z; p[3]=p4.w;

    float s1 = g_ssq[row];
    #pragma unroll
    for (int k = 0; k < 4; k++) s1 += 2.0f * h[k] * p[k];
    #pragma unroll
    for (int k = 0; k < 4; k++)
        #pragma unroll
        for (int q = 0; q < 4; q++) s1 += h[k] * h[q] * sG[k*4+q];
    float scale = rsqrtf(s1 * (1.0f/DD) + EPS);

    #pragma unroll
    for (int r = 0; r < RFF; r++){
        float t = g_pw1[(size_t)row*RFF + r];
        #pragma unroll
        for (int k = 0; k < 4; k++) t += h[k] * sM[k*16 + r];
        g_g[(size_t)row*RFF + r] = gelu_tanh(t * scale);
    }
}

// ======================= k_main: out = x + U h + g @ W2 =======================
// 256 threads, 2 CTA/SM; thread owns one ulonglong2 (4 floats); 16 rows/block.
// grid = (NROWS/TRM, DD/4/256 = 2)
__global__ void __launch_bounds__(256, 2) k_main(const float* __restrict__ x,
                                                 const float* __restrict__ W2,
                                                 float* __restrict__ out){
    const int row0 = blockIdx.x * TRM;
    const int tid  = threadIdx.x;
    const int q    = blockIdx.y * 256 + tid;   // ulonglong2 index within row (0..511)

    ulonglong2 ut[4], w2[16];
    #pragma unroll
    for (int k = 0; k < 4; k++)
        ut[k] = reinterpret_cast<const ulonglong2*>(g_Ut)[k*(DD/4) + q];
    #pragma unroll
    for (int r = 0; r < RFF; r++)
        w2[r] = reinterpret_cast<const ulonglong2*>(W2)[r*(DD/4) + q];

    __shared__ __align__(16) float hs[TRM][20];
    for (int i = tid; i < TRM*20; i += 256){
        int row = i / 20, j = i % 20;
        hs[row][j] = (j < 4) ? g_h[j*NROWS + row0 + row]
                             : g_g[(size_t)(row0+row)*RFF + (j-4)];
    }
    __syncthreads();

    const ulonglong2* xr = reinterpret_cast<const ulonglong2*>(x)   + (size_t)row0*(DD/4) + q;
    ulonglong2*       op = reinterpret_cast<ulonglong2*>(out)       + (size_t)row0*(DD/4) + q;

    ulonglong2 xa = xr[0];
    #pragma unroll
    for (int row = 0; row < TRM; row++){
        ulonglong2 xn = xa;
        if (row + 1 < TRM) xn = xr[(size_t)(row+1)*(DD/4)];

        float sc[20];
        float4* sc4 = reinterpret_cast<float4*>(sc);
        const float4* hp = reinterpret_cast<const float4*>(&hs[row][0]);
        #pragma unroll
        for (int i = 0; i < 5; i++) sc4[i] = hp[i];

        u64 a0 = xa.x, a1 = xa.y, b0 = 0ull, b1 = 0ull;
        #pragma unroll
        for (int k = 0; k < 4; k++){
            u64 s = pack2(sc[k], sc[k]);
            if (k & 1){ b0 = fma2(s, ut[k].x, b0); b1 = fma2(s, ut[k].y, b1); }
            else      { a0 = fma2(s, ut[k].x, a0); a1 = fma2(s, ut[k].y, a1); }
        }
        #pragma unroll
        for (int r = 0; r < RFF; r++){
            u64 s = pack2(sc[4+r], sc[4+r]);
            if (r & 1){ b0 = fma2(s, w2[r].x, b0); b1 = fma2(s, w2[r].y, b1); }
            else      { a0 = fma2(s, w2[r].x, a0); a1 = fma2(s, w2[r].y, a1); }
        }
        ulonglong2 o;
        o.x = add2(a0, b0);
        o.y = add2(a1, b1);
        op[(size_t)row*(DD/4)] = o;
        xa = xn;
    }
}

// ======================= launch =======================
extern "C" void kernel_launch(void* const* d_in, const int* in_sizes, int n_in,
                              void* d_out, int out_size){
    const float* x       = (const float*)d_in[0];
    const float* norm_w  = (const float*)d_in[1];
    const float* V       = (const float*)d_in[2];
    const float* U       = (const float*)d_in[3];
    const float* a_logit = (const float*)d_in[4];
    const float* W1      = (const float*)d_in[5];
    const float* W2      = (const float*)d_in[6];
    float* out = (float*)d_out;

    k_prep_all<<<88, 256>>>(norm_w, V, U, a_logit, W1);
    k_u    <<<NROWS/TRU, 512>>>(x);
    k_scan <<<BB*RR, 256>>>();
    k_post <<<NROWS/256, 256>>>();
    dim3 gm(NROWS/TRM, 2);
    k_main <<<gm, 256>>>(x, W2, out);
}